// round 2
// baseline (speedup 1.0000x reference)
#include <cuda_runtime.h>
#include <cstdint>

#define NN 50000
#define EE 800000
#define NDROP 3200000u   // NN*64 dropout elements

// ---------------- static scratch (no allocation allowed) ----------------
__device__ int   d_is64;
__device__ int   d_deg[NN];
__device__ int   d_row_ptr[NN + 1];
__device__ int   d_cursor[NN];
__device__ int   d_csr[EE];
__device__ float d_dinv[NN];
__device__ float d_bufA[(size_t)NN * 256];
__device__ float d_bufB[(size_t)NN * 256];

__device__ __forceinline__ float* bufptr(int s) { return s == 0 ? d_bufA : d_bufB; }

// ---------------- preprocessing ----------------
__global__ void detect_kernel(const unsigned* __restrict__ e) {
    if (threadIdx.x == 0 && blockIdx.x == 0) {
        int is64 = 1;
        for (int i = 0; i < 64; i++) {
            if (e[2 * i + 1] != 0u) { is64 = 0; break; }
        }
        d_is64 = is64;
    }
}

__global__ void zero_deg_kernel() {
    int i = blockIdx.x * blockDim.x + threadIdx.x;
    if (i < NN) d_deg[i] = 0;
}

__global__ void count_deg_kernel(const unsigned* __restrict__ e) {
    int i = blockIdx.x * blockDim.x + threadIdx.x;
    if (i >= EE) return;
    int dst = d_is64 ? (int)e[2 * (size_t)(EE + i)] : (int)e[EE + i];
    atomicAdd(&d_deg[dst], 1);
}

// single-block exclusive scan over deg -> row_ptr, cursor; also dinv = (deg+1)^-1/2
__global__ void scan_kernel() {
    __shared__ int warp_sums[32];
    __shared__ int carry_sh;
    int t = threadIdx.x;
    int lane = t & 31, wid = t >> 5;
    if (t == 0) carry_sh = 0;
    __syncthreads();
    for (int base = 0; base < NN; base += 1024) {
        int i = base + t;
        int v = (i < NN) ? d_deg[i] : 0;
        int x = v;
        #pragma unroll
        for (int o = 1; o < 32; o <<= 1) {
            int y = __shfl_up_sync(0xFFFFFFFFu, x, o);
            if (lane >= o) x += y;
        }
        if (lane == 31) warp_sums[wid] = x;
        __syncthreads();
        if (wid == 0) {
            int s = warp_sums[lane];
            #pragma unroll
            for (int o = 1; o < 32; o <<= 1) {
                int y = __shfl_up_sync(0xFFFFFFFFu, s, o);
                if (lane >= o) s += y;
            }
            warp_sums[lane] = s;
        }
        __syncthreads();
        int warp_off = (wid == 0) ? 0 : warp_sums[wid - 1];
        int excl = carry_sh + warp_off + (x - v);
        if (i < NN) {
            d_row_ptr[i] = excl;
            d_cursor[i]  = excl;
            d_dinv[i]    = rsqrtf((float)(v + 1));
        }
        __syncthreads();
        if (t == 0) carry_sh += warp_sums[31];
        __syncthreads();
    }
    if (t == 0) d_row_ptr[NN] = carry_sh;
}

__global__ void fill_csr_kernel(const unsigned* __restrict__ e) {
    int i = blockIdx.x * blockDim.x + threadIdx.x;
    if (i >= EE) return;
    int src, dst;
    if (d_is64) {
        src = (int)e[2 * (size_t)i];
        dst = (int)e[2 * (size_t)(EE + i)];
    } else {
        src = (int)e[i];
        dst = (int)e[EE + i];
    }
    int pos = atomicAdd(&d_cursor[dst], 1);
    d_csr[pos] = src;
}

// ---------------- GEMM: C[m][n] = dinv[m] * sum_k A[m][k] W[k][n] ----------------
#define BM 64
#define BN 64
#define BKK 16

__global__ __launch_bounds__(256) void gemm_scale_kernel(
    const float* __restrict__ Aext, int selA, int selC,
    const float* __restrict__ W, int M, int K, int Nn)
{
    const float* A = Aext ? Aext : bufptr(selA);
    float* C = bufptr(selC);

    __shared__ float As[BKK][BM + 4];
    __shared__ float Ws[BKK][BN];

    int tid = threadIdx.x;
    int tx = tid & 15, ty = tid >> 4;
    int m0 = blockIdx.x * BM, n0 = blockIdx.y * BN;

    float acc[4][4] = {};

    int la_row = tid >> 2;          // 0..63
    int la_k4  = (tid & 3) * 4;     // 0,4,8,12
    int lw_k   = tid >> 4;          // 0..15
    int lw_n4  = (tid & 15) * 4;    // 0..60

    for (int k0 = 0; k0 < K; k0 += BKK) {
        int m = m0 + la_row;
        float4 av = make_float4(0.f, 0.f, 0.f, 0.f);
        if (m < M) av = *(const float4*)(A + (size_t)m * K + k0 + la_k4);
        As[la_k4 + 0][la_row] = av.x;
        As[la_k4 + 1][la_row] = av.y;
        As[la_k4 + 2][la_row] = av.z;
        As[la_k4 + 3][la_row] = av.w;

        float4 wv = *(const float4*)(W + (size_t)(k0 + lw_k) * Nn + n0 + lw_n4);
        *(float4*)&Ws[lw_k][lw_n4] = wv;
        __syncthreads();

        #pragma unroll
        for (int kk = 0; kk < BKK; kk++) {
            float4 a = *(const float4*)&As[kk][ty * 4];
            float4 b = *(const float4*)&Ws[kk][tx * 4];
            float ar[4] = {a.x, a.y, a.z, a.w};
            float br[4] = {b.x, b.y, b.z, b.w};
            #pragma unroll
            for (int i = 0; i < 4; i++)
                #pragma unroll
                for (int j = 0; j < 4; j++)
                    acc[i][j] += ar[i] * br[j];
        }
        __syncthreads();
    }

    #pragma unroll
    for (int i = 0; i < 4; i++) {
        int m = m0 + ty * 4 + i;
        if (m < M) {
            float dv = d_dinv[m];
            float4 o = make_float4(acc[i][0] * dv, acc[i][1] * dv,
                                   acc[i][2] * dv, acc[i][3] * dv);
            *(float4*)(C + (size_t)m * Nn + n0 + tx * 4) = o;
        }
    }
}

// ---------------- CSR aggregation + bias + leaky_relu ----------------
// out[i][f] = lrelu( dinv[i] * (h'[i][f] + sum_nbr h'[src][f]) + b[f] )
__global__ void aggregate_kernel(int selIn, int selOut,
                                 const float* __restrict__ bias, int F, int relu)
{
    const float* h = bufptr(selIn);
    float* out = bufptr(selOut);
    __shared__ int nbr[256];

    int i = blockIdx.x;
    int f = threadIdx.x;              // blockDim.x == F
    int p0 = d_row_ptr[i], p1 = d_row_ptr[i + 1];

    float acc = h[(size_t)i * F + f]; // self-loop term (pre-scaled by dinv_i)
    for (int base = p0; base < p1; base += blockDim.x) {
        int cnt = min((int)blockDim.x, p1 - base);
        if (f < cnt) nbr[f] = d_csr[base + f];
        __syncthreads();
        for (int j = 0; j < cnt; j++)
            acc += h[(size_t)nbr[j] * F + f];
        __syncthreads();
    }
    float v = d_dinv[i] * acc + bias[f];
    if (relu) v = (v >= 0.f) ? v : 0.01f * v;
    out[(size_t)i * F + f] = v;
}

// ---------------- dropout: JAX threefry2x32 PARTITIONABLE mode, key(42), p=0.5 ----
// Modern JAX (jax_threefry_partitionable=True, default since 0.5): per-element
// 64-bit counter idx -> (hi=idx>>32, lo=idx); bits32 = out0 ^ out1.
// keep iff uniform < 0.5 iff top bit of bits32 == 0.
#define TF_RND(r) { x0 += x1; x1 = (x1 << r) | (x1 >> (32 - r)); x1 ^= x0; }

__global__ void dropout_kernel(int sel) {
    float* h = bufptr(sel);
    unsigned t = blockIdx.x * blockDim.x + threadIdx.x;
    if (t >= NDROP) return;
    unsigned x0 = 0u;      // hi word of 64-bit counter (always 0 for idx < 2^32)
    unsigned x1 = t;       // lo word
    const unsigned ks0 = 0u, ks1 = 42u, ks2 = 0u ^ 42u ^ 0x1BD11BDAu;
    x0 += ks0; x1 += ks1;
    TF_RND(13) TF_RND(15) TF_RND(26) TF_RND(6)   x0 += ks1; x1 += ks2 + 1u;
    TF_RND(17) TF_RND(29) TF_RND(16) TF_RND(24)  x0 += ks2; x1 += ks0 + 2u;
    TF_RND(13) TF_RND(15) TF_RND(26) TF_RND(6)   x0 += ks0; x1 += ks1 + 3u;
    TF_RND(17) TF_RND(29) TF_RND(16) TF_RND(24)  x0 += ks1; x1 += ks2 + 4u;
    TF_RND(13) TF_RND(15) TF_RND(26) TF_RND(6)   x0 += ks2; x1 += ks0 + 5u;
    unsigned draw = x0 ^ x1;
    h[t] = (draw >> 31) ? 0.0f : h[t] * 2.0f;
}

// ---------------- final tiny GEMM: out[M,10] = h[M,64] @ W5[64,10] + b5 ----------------
__global__ __launch_bounds__(256) void final_gemm_kernel(
    int sel, const float* __restrict__ W, const float* __restrict__ b,
    float* __restrict__ out, int M)
{
    const float* h = bufptr(sel);
    __shared__ float Xs[64 * 64];
    __shared__ float Ws[64 * 10];
    __shared__ float bs[10];
    int t = threadIdx.x;
    int m0 = blockIdx.x * 64;

    for (int idx = t; idx < 640; idx += 256) Ws[idx] = W[idx];
    if (t < 10) bs[t] = b[t];
    for (int idx = t; idx < 64 * 16; idx += 256) {   // 64 rows x 16 float4
        int row = idx >> 4, c4 = idx & 15;
        int m = m0 + row;
        float4 v = make_float4(0.f, 0.f, 0.f, 0.f);
        if (m < M) v = ((const float4*)h)[(size_t)m * 16 + c4];
        ((float4*)Xs)[row * 16 + c4] = v;
    }
    __syncthreads();

    for (int o = t; o < 640; o += 256) {
        int row = o / 10, col = o % 10;
        int m = m0 + row;
        if (m < M) {
            float s = bs[col];
            #pragma unroll 8
            for (int k = 0; k < 64; k++)
                s += Xs[row * 64 + k] * Ws[k * 10 + col];
            out[(size_t)m * 10 + col] = s;
        }
    }
}

// ---------------- launch ----------------
extern "C" void kernel_launch(void* const* d_in, const int* in_sizes, int n_in,
                              void* d_out, int out_size)
{
    const float*    x     = (const float*)d_in[0];
    const unsigned* edges = (const unsigned*)d_in[1];
    const float* W1 = (const float*)d_in[2];  const float* b1 = (const float*)d_in[3];
    const float* W2 = (const float*)d_in[4];  const float* b2 = (const float*)d_in[5];
    const float* W3 = (const float*)d_in[6];  const float* b3 = (const float*)d_in[7];
    const float* W4 = (const float*)d_in[8];  const float* b4 = (const float*)d_in[9];
    const float* W5 = (const float*)d_in[10]; const float* b5 = (const float*)d_in[11];

    const int M = NN;
    const int gm = (M + BM - 1) / BM;   // 782

    detect_kernel<<<1, 32>>>(edges);
    zero_deg_kernel<<<(NN + 255) / 256, 256>>>();
    count_deg_kernel<<<(EE + 255) / 256, 256>>>(edges);
    scan_kernel<<<1, 1024>>>();
    fill_csr_kernel<<<(EE + 255) / 256, 256>>>(edges);

    // layer 1: X(ext,256) -> A ; agg -> B   (F=256)
    gemm_scale_kernel<<<dim3(gm, 4), 256>>>(x, 0, 0, W1, M, 256, 256);
    aggregate_kernel<<<M, 256>>>(0, 1, b1, 256, 1);
    // layer 2: B -> A ; agg -> B            (F=256)
    gemm_scale_kernel<<<dim3(gm, 4), 256>>>(nullptr, 1, 0, W2, M, 256, 256);
    aggregate_kernel<<<M, 256>>>(0, 1, b2, 256, 1);
    // layer 3: B(256) -> A(128) ; agg -> B  (F=128)
    gemm_scale_kernel<<<dim3(gm, 2), 256>>>(nullptr, 1, 0, W3, M, 256, 128);
    aggregate_kernel<<<M, 128>>>(0, 1, b3, 128, 1);
    // layer 4: B(128) -> A(64) ; agg -> B   (F=64)
    gemm_scale_kernel<<<dim3(gm, 1), 256>>>(nullptr, 1, 0, W4, M, 128, 64);
    aggregate_kernel<<<M, 64>>>(0, 1, b4, 64, 1);
    // dropout on B (50000 x 64), threefry partitionable, key(42)
    dropout_kernel<<<(NDROP + 255) / 256, 256>>>(1);
    // final: B @ W5 + b5 -> d_out
    final_gemm_kernel<<<gm, 256>>>(1, W5, b5, (float*)d_out, M);
}

// round 3
// speedup vs baseline: 1.1636x; 1.1636x over previous
#include <cuda_runtime.h>
#include <cstdint>

#define NN 50000
#define EE 800000
#define NDROP 3200000u   // NN*64 dropout elements
#define SCAN_B 256
#define NBLK ((NN + SCAN_B - 1) / SCAN_B)   // 196

// ---------------- static scratch (no allocation allowed) ----------------
__device__ int   d_is64;
__device__ int   d_deg[NN];
__device__ int   d_row_ptr[NN + 1];
__device__ int   d_cursor[NN];
__device__ int   d_csr[EE];
__device__ float d_dinv[NN];
__device__ int   d_blksum[NBLK];
__device__ int   d_blkoff[NBLK];
__device__ float d_bufA[(size_t)NN * 256];
__device__ float d_bufB[(size_t)NN * 256];

__device__ __forceinline__ float* bufptr(int s) { return s == 0 ? d_bufA : d_bufB; }

// ---------------- preprocessing ----------------
__global__ void detect_kernel(const unsigned* __restrict__ e) {
    if (threadIdx.x == 0 && blockIdx.x == 0) {
        int is64 = 1;
        for (int i = 0; i < 64; i++) {
            if (e[2 * i + 1] != 0u) { is64 = 0; break; }
        }
        d_is64 = is64;
    }
}

__global__ void zero_deg_kernel() {
    int i = blockIdx.x * blockDim.x + threadIdx.x;
    if (i < NN) d_deg[i] = 0;
}

__global__ void count_deg_kernel(const unsigned* __restrict__ e) {
    int i = blockIdx.x * blockDim.x + threadIdx.x;
    if (i >= EE) return;
    int dst = d_is64 ? (int)e[2 * (size_t)(EE + i)] : (int)e[EE + i];
    atomicAdd(&d_deg[dst], 1);
}

// -- parallel 3-phase exclusive scan over deg --
__global__ void deg_blocksum_kernel() {           // grid NBLK x 256
    __shared__ int wsum[8];
    int i = blockIdx.x * SCAN_B + threadIdx.x;
    int v = (i < NN) ? d_deg[i] : 0;
    int lane = threadIdx.x & 31, wid = threadIdx.x >> 5;
    int x = v;
    #pragma unroll
    for (int o = 16; o > 0; o >>= 1) x += __shfl_down_sync(0xFFFFFFFFu, x, o);
    if (lane == 0) wsum[wid] = x;
    __syncthreads();
    if (threadIdx.x == 0) {
        int s = 0;
        #pragma unroll
        for (int w = 0; w < 8; w++) s += wsum[w];
        d_blksum[blockIdx.x] = s;
    }
}

__global__ void scan_blocks_kernel() {            // 1 block x 256
    __shared__ int wsum[8];
    int t = threadIdx.x;
    int lane = t & 31, wid = t >> 5;
    int v = (t < NBLK) ? d_blksum[t] : 0;
    int x = v;
    #pragma unroll
    for (int o = 1; o < 32; o <<= 1) {
        int y = __shfl_up_sync(0xFFFFFFFFu, x, o);
        if (lane >= o) x += y;
    }
    if (lane == 31) wsum[wid] = x;
    __syncthreads();
    if (wid == 0 && lane < 8) {
        int s = wsum[lane];
        #pragma unroll
        for (int o = 1; o < 8; o <<= 1) {
            int y = __shfl_up_sync(0xFFu, s, o);
            if (lane >= o) s += y;
        }
        wsum[lane] = s;
    }
    __syncthreads();
    int woff = (wid == 0) ? 0 : wsum[wid - 1];
    if (t < NBLK) d_blkoff[t] = woff + (x - v);
    if (t == 0) d_row_ptr[NN] = EE;
}

__global__ void scatter_scan_kernel() {           // grid NBLK x 256
    __shared__ int wsum[8];
    int t = threadIdx.x;
    int lane = t & 31, wid = t >> 5;
    int i = blockIdx.x * SCAN_B + t;
    int v = (i < NN) ? d_deg[i] : 0;
    int x = v;
    #pragma unroll
    for (int o = 1; o < 32; o <<= 1) {
        int y = __shfl_up_sync(0xFFFFFFFFu, x, o);
        if (lane >= o) x += y;
    }
    if (lane == 31) wsum[wid] = x;
    __syncthreads();
    if (wid == 0 && lane < 8) {
        int s = wsum[lane];
        #pragma unroll
        for (int o = 1; o < 8; o <<= 1) {
            int y = __shfl_up_sync(0xFFu, s, o);
            if (lane >= o) s += y;
        }
        wsum[lane] = s;
    }
    __syncthreads();
    int woff = (wid == 0) ? 0 : wsum[wid - 1];
    if (i < NN) {
        int excl = d_blkoff[blockIdx.x] + woff + (x - v);
        d_row_ptr[i] = excl;
        d_cursor[i]  = excl;
        d_dinv[i]    = rsqrtf((float)(v + 1));
    }
}

__global__ void fill_csr_kernel(const unsigned* __restrict__ e) {
    int i = blockIdx.x * blockDim.x + threadIdx.x;
    if (i >= EE) return;
    int src, dst;
    if (d_is64) {
        src = (int)e[2 * (size_t)i];
        dst = (int)e[2 * (size_t)(EE + i)];
    } else {
        src = (int)e[i];
        dst = (int)e[EE + i];
    }
    int pos = atomicAdd(&d_cursor[dst], 1);
    d_csr[pos] = src;
}

// ---------------- tensor-core GEMM (3xTF32): C[m][n] = dinv[m]*sum A W ---------
#define GBM 128
#define GBN 64
#define GBK 32

__device__ __forceinline__ void mma_tf32(float* d, const unsigned* a, const unsigned* b) {
    asm volatile(
        "mma.sync.aligned.m16n8k8.row.col.f32.tf32.tf32.f32 "
        "{%0,%1,%2,%3}, {%4,%5,%6,%7}, {%8,%9}, {%0,%1,%2,%3};\n"
        : "+f"(d[0]), "+f"(d[1]), "+f"(d[2]), "+f"(d[3])
        : "r"(a[0]), "r"(a[1]), "r"(a[2]), "r"(a[3]),
          "r"(b[0]), "r"(b[1]));
}

__device__ __forceinline__ void split_tf32(float v, unsigned& hi, unsigned& lo) {
    unsigned h;
    asm("cvt.rna.tf32.f32 %0, %1;" : "=r"(h) : "f"(v));
    float r = v - __uint_as_float(h);
    asm("cvt.rna.tf32.f32 %0, %1;" : "=r"(lo) : "f"(r));
    hi = h;
}

__global__ __launch_bounds__(256) void gemm_tf32_kernel(
    const float* __restrict__ Aext, int selA, int selC,
    const float* __restrict__ W, int M, int K, int Nn)
{
    const float* A = Aext ? Aext : bufptr(selA);
    float* C = bufptr(selC);

    __shared__ float As[GBM][GBK + 4];   // row stride 36 -> conflict-free frag loads
    __shared__ float Bs[GBK][GBN + 4];   // row stride 68

    int tid = threadIdx.x;
    int warp = tid >> 5, lane = tid & 31;
    int g = lane >> 2, tig = lane & 3;
    int warpM = warp >> 1, warpN = warp & 1;     // 4(m) x 2(n) warps
    int m0 = blockIdx.x * GBM, n0 = blockIdx.y * GBN;

    float acc[2][4][4];
    #pragma unroll
    for (int i = 0; i < 2; i++)
        #pragma unroll
        for (int j = 0; j < 4; j++)
            #pragma unroll
            for (int c = 0; c < 4; c++) acc[i][j][c] = 0.f;

    int ar  = tid >> 3;           // 0..31
    int ac4 = (tid & 7) * 4;      // 0..28
    int bk  = tid >> 4;           // 0..15
    int bn4 = (tid & 15) * 4;     // 0..60

    for (int k0 = 0; k0 < K; k0 += GBK) {
        #pragma unroll
        for (int rr = 0; rr < 4; rr++) {
            int row = rr * 32 + ar;
            int m = m0 + row;
            float4 v = make_float4(0.f, 0.f, 0.f, 0.f);
            if (m < M) v = *(const float4*)(A + (size_t)m * K + k0 + ac4);
            *(float4*)&As[row][ac4] = v;
        }
        #pragma unroll
        for (int rr = 0; rr < 2; rr++) {
            int kk = rr * 16 + bk;
            float4 v = *(const float4*)(W + (size_t)(k0 + kk) * Nn + n0 + bn4);
            *(float4*)&Bs[kk][bn4] = v;
        }
        __syncthreads();

        #pragma unroll
        for (int ks = 0; ks < GBK; ks += 8) {
            unsigned aHi[2][4], aLo[2][4];
            #pragma unroll
            for (int ma = 0; ma < 2; ma++) {
                int rb = warpM * 32 + ma * 16;
                split_tf32(As[rb + g    ][ks + tig    ], aHi[ma][0], aLo[ma][0]);
                split_tf32(As[rb + g + 8][ks + tig    ], aHi[ma][1], aLo[ma][1]);
                split_tf32(As[rb + g    ][ks + tig + 4], aHi[ma][2], aLo[ma][2]);
                split_tf32(As[rb + g + 8][ks + tig + 4], aHi[ma][3], aLo[ma][3]);
            }
            unsigned bHi[4][2], bLo[4][2];
            #pragma unroll
            for (int na = 0; na < 4; na++) {
                int nc = warpN * 32 + na * 8 + g;
                split_tf32(Bs[ks + tig    ][nc], bHi[na][0], bLo[na][0]);
                split_tf32(Bs[ks + tig + 4][nc], bHi[na][1], bLo[na][1]);
            }
            #pragma unroll
            for (int ma = 0; ma < 2; ma++)
                #pragma unroll
                for (int na = 0; na < 4; na++) {
                    mma_tf32(acc[ma][na], aHi[ma], bHi[na]);
                    mma_tf32(acc[ma][na], aHi[ma], bLo[na]);
                    mma_tf32(acc[ma][na], aLo[ma], bHi[na]);
                }
        }
        __syncthreads();
    }

    #pragma unroll
    for (int ma = 0; ma < 2; ma++) {
        int rb = m0 + warpM * 32 + ma * 16 + g;
        #pragma unroll
        for (int half = 0; half < 2; half++) {
            int row = rb + half * 8;
            if (row < M) {
                float dv = d_dinv[row];
                #pragma unroll
                for (int na = 0; na < 4; na++) {
                    int col = n0 + warpN * 32 + na * 8 + tig * 2;
                    float2 o;
                    o.x = acc[ma][na][half * 2 + 0] * dv;
                    o.y = acc[ma][na][half * 2 + 1] * dv;
                    *(float2*)(C + (size_t)row * Nn + col) = o;
                }
            }
        }
    }
}

// ---------------- CSR aggregation + bias + leaky_relu ----------------
__global__ void aggregate_kernel(int selIn, int selOut,
                                 const float* __restrict__ bias, int F, int relu)
{
    const float* h = bufptr(selIn);
    float* out = bufptr(selOut);
    __shared__ int nbr[256];

    int i = blockIdx.x;
    int f = threadIdx.x;              // blockDim.x == F
    int p0 = d_row_ptr[i], p1 = d_row_ptr[i + 1];

    float acc = h[(size_t)i * F + f]; // self-loop term (pre-scaled by dinv_i)
    for (int base = p0; base < p1; base += blockDim.x) {
        int cnt = min((int)blockDim.x, p1 - base);
        if (f < cnt) nbr[f] = d_csr[base + f];
        __syncthreads();
        for (int j = 0; j < cnt; j++)
            acc += h[(size_t)nbr[j] * F + f];
        __syncthreads();
    }
    float v = d_dinv[i] * acc + bias[f];
    if (relu) v = (v >= 0.f) ? v : 0.01f * v;
    out[(size_t)i * F + f] = v;
}

// ---------------- dropout: JAX threefry2x32 partitionable, key(42), p=0.5 ----
#define TF_RND(r) { x0 += x1; x1 = (x1 << r) | (x1 >> (32 - r)); x1 ^= x0; }

__global__ void dropout_kernel(int sel) {
    float* h = bufptr(sel);
    unsigned t = blockIdx.x * blockDim.x + threadIdx.x;
    if (t >= NDROP) return;
    unsigned x0 = 0u;      // hi word of 64-bit counter
    unsigned x1 = t;       // lo word
    const unsigned ks0 = 0u, ks1 = 42u, ks2 = 0u ^ 42u ^ 0x1BD11BDAu;
    x0 += ks0; x1 += ks1;
    TF_RND(13) TF_RND(15) TF_RND(26) TF_RND(6)   x0 += ks1; x1 += ks2 + 1u;
    TF_RND(17) TF_RND(29) TF_RND(16) TF_RND(24)  x0 += ks2; x1 += ks0 + 2u;
    TF_RND(13) TF_RND(15) TF_RND(26) TF_RND(6)   x0 += ks0; x1 += ks1 + 3u;
    TF_RND(17) TF_RND(29) TF_RND(16) TF_RND(24)  x0 += ks1; x1 += ks2 + 4u;
    TF_RND(13) TF_RND(15) TF_RND(26) TF_RND(6)   x0 += ks2; x1 += ks0 + 5u;
    unsigned draw = x0 ^ x1;
    h[t] = (draw >> 31) ? 0.0f : h[t] * 2.0f;
}

// ---------------- final tiny GEMM: out[M,10] = h[M,64] @ W5[64,10] + b5 -------
__global__ __launch_bounds__(256) void final_gemm_kernel(
    int sel, const float* __restrict__ W, const float* __restrict__ b,
    float* __restrict__ out, int M)
{
    const float* h = bufptr(sel);
    __shared__ float Xs[64 * 64];
    __shared__ float Ws[64 * 10];
    __shared__ float bs[10];
    int t = threadIdx.x;
    int m0 = blockIdx.x * 64;

    for (int idx = t; idx < 640; idx += 256) Ws[idx] = W[idx];
    if (t < 10) bs[t] = b[t];
    for (int idx = t; idx < 64 * 16; idx += 256) {
        int row = idx >> 4, c4 = idx & 15;
        int m = m0 + row;
        float4 v = make_float4(0.f, 0.f, 0.f, 0.f);
        if (m < M) v = ((const float4*)h)[(size_t)m * 16 + c4];
        ((float4*)Xs)[row * 16 + c4] = v;
    }
    __syncthreads();

    for (int o = t; o < 640; o += 256) {
        int row = o / 10, col = o % 10;
        int m = m0 + row;
        if (m < M) {
            float s = bs[col];
            #pragma unroll 8
            for (int k = 0; k < 64; k++)
                s += Xs[row * 64 + k] * Ws[k * 10 + col];
            out[(size_t)m * 10 + col] = s;
        }
    }
}

// ---------------- launch ----------------
extern "C" void kernel_launch(void* const* d_in, const int* in_sizes, int n_in,
                              void* d_out, int out_size)
{
    const float*    x     = (const float*)d_in[0];
    const unsigned* edges = (const unsigned*)d_in[1];
    const float* W1 = (const float*)d_in[2];  const float* b1 = (const float*)d_in[3];
    const float* W2 = (const float*)d_in[4];  const float* b2 = (const float*)d_in[5];
    const float* W3 = (const float*)d_in[6];  const float* b3 = (const float*)d_in[7];
    const float* W4 = (const float*)d_in[8];  const float* b4 = (const float*)d_in[9];
    const float* W5 = (const float*)d_in[10]; const float* b5 = (const float*)d_in[11];

    const int M = NN;
    const int gm = (M + GBM - 1) / GBM;   // 391
    const int gfin = (M + 63) / 64;       // 782

    detect_kernel<<<1, 32>>>(edges);
    zero_deg_kernel<<<(NN + 255) / 256, 256>>>();
    count_deg_kernel<<<(EE + 255) / 256, 256>>>(edges);
    deg_blocksum_kernel<<<NBLK, SCAN_B>>>();
    scan_blocks_kernel<<<1, 256>>>();
    scatter_scan_kernel<<<NBLK, SCAN_B>>>();
    fill_csr_kernel<<<(EE + 255) / 256, 256>>>(edges);

    // layer 1: X(ext,256) -> A ; agg -> B   (F=256)
    gemm_tf32_kernel<<<dim3(gm, 4), 256>>>(x, 0, 0, W1, M, 256, 256);
    aggregate_kernel<<<M, 256>>>(0, 1, b1, 256, 1);
    // layer 2: B -> A ; agg -> B            (F=256)
    gemm_tf32_kernel<<<dim3(gm, 4), 256>>>(nullptr, 1, 0, W2, M, 256, 256);
    aggregate_kernel<<<M, 256>>>(0, 1, b2, 256, 1);
    // layer 3: B(256) -> A(128) ; agg -> B  (F=128)
    gemm_tf32_kernel<<<dim3(gm, 2), 256>>>(nullptr, 1, 0, W3, M, 256, 128);
    aggregate_kernel<<<M, 128>>>(0, 1, b3, 128, 1);
    // layer 4: B(128) -> A(64) ; agg -> B   (F=64)
    gemm_tf32_kernel<<<dim3(gm, 1), 256>>>(nullptr, 1, 0, W4, M, 128, 64);
    aggregate_kernel<<<M, 64>>>(0, 1, b4, 64, 1);
    // dropout on B (50000 x 64), threefry partitionable, key(42)
    dropout_kernel<<<(NDROP + 255) / 256, 256>>>(1);
    // final: B @ W5 + b5 -> d_out
    final_gemm_kernel<<<gfin, 256>>>(1, W5, b5, (float*)d_out, M);
}

// round 5
// speedup vs baseline: 1.9727x; 1.6953x over previous
#include <cuda_runtime.h>
#include <cuda_bf16.h>
#include <cstdint>

#define NN 50000
#define EE 800000
#define SCAN_B 256
#define NBLK ((NN + SCAN_B - 1) / SCAN_B)   // 196

// ---------------- static scratch (no allocation allowed) ----------------
__device__ int   d_is64;
__device__ int   d_deg[NN];
__device__ int   d_row_ptr[NN + 1];
__device__ int   d_cursor[NN];
__device__ int   d_csr[EE];
__device__ float d_dinv[NN];
__device__ int   d_blksum[NBLK];
__device__ int   d_blkoff[NBLK];
__device__ float d_bufA[(size_t)NN * 256];
__device__ float d_bufB[(size_t)NN * 256];

__device__ __forceinline__ float* bufptr(int s) { return s == 0 ? d_bufA : d_bufB; }

// ---------------- preprocessing ----------------
__global__ void detect_kernel(const unsigned* __restrict__ e) {
    if (threadIdx.x == 0 && blockIdx.x == 0) {
        int is64 = 1;
        for (int i = 0; i < 64; i++) {
            if (e[2 * i + 1] != 0u) { is64 = 0; break; }
        }
        d_is64 = is64;
    }
}

__global__ void zero_deg_kernel() {
    int i = blockIdx.x * blockDim.x + threadIdx.x;
    if (i < NN) d_deg[i] = 0;
}

__global__ void count_deg_kernel(const unsigned* __restrict__ e) {
    int i = blockIdx.x * blockDim.x + threadIdx.x;
    if (i >= EE) return;
    int dst = d_is64 ? (int)e[2 * (size_t)(EE + i)] : (int)e[EE + i];
    atomicAdd(&d_deg[dst], 1);
}

__global__ void deg_blocksum_kernel() {
    __shared__ int wsum[8];
    int i = blockIdx.x * SCAN_B + threadIdx.x;
    int v = (i < NN) ? d_deg[i] : 0;
    int lane = threadIdx.x & 31, wid = threadIdx.x >> 5;
    int x = v;
    #pragma unroll
    for (int o = 16; o > 0; o >>= 1) x += __shfl_down_sync(0xFFFFFFFFu, x, o);
    if (lane == 0) wsum[wid] = x;
    __syncthreads();
    if (threadIdx.x == 0) {
        int s = 0;
        #pragma unroll
        for (int w = 0; w < 8; w++) s += wsum[w];
        d_blksum[blockIdx.x] = s;
    }
}

__global__ void scan_blocks_kernel() {
    __shared__ int wsum[8];
    int t = threadIdx.x;
    int lane = t & 31, wid = t >> 5;
    int v = (t < NBLK) ? d_blksum[t] : 0;
    int x = v;
    #pragma unroll
    for (int o = 1; o < 32; o <<= 1) {
        int y = __shfl_up_sync(0xFFFFFFFFu, x, o);
        if (lane >= o) x += y;
    }
    if (lane == 31) wsum[wid] = x;
    __syncthreads();
    if (wid == 0 && lane < 8) {
        int s = wsum[lane];
        #pragma unroll
        for (int o = 1; o < 8; o <<= 1) {
            int y = __shfl_up_sync(0xFFu, s, o);
            if (lane >= o) s += y;
        }
        wsum[lane] = s;
    }
    __syncthreads();
    int woff = (wid == 0) ? 0 : wsum[wid - 1];
    if (t < NBLK) d_blkoff[t] = woff + (x - v);
    if (t == 0) d_row_ptr[NN] = EE;
}

__global__ void scatter_scan_kernel() {
    __shared__ int wsum[8];
    int t = threadIdx.x;
    int lane = t & 31, wid = t >> 5;
    int i = blockIdx.x * SCAN_B + t;
    int v = (i < NN) ? d_deg[i] : 0;
    int x = v;
    #pragma unroll
    for (int o = 1; o < 32; o <<= 1) {
        int y = __shfl_up_sync(0xFFFFFFFFu, x, o);
        if (lane >= o) x += y;
    }
    if (lane == 31) wsum[wid] = x;
    __syncthreads();
    if (wid == 0 && lane < 8) {
        int s = wsum[lane];
        #pragma unroll
        for (int o = 1; o < 8; o <<= 1) {
            int y = __shfl_up_sync(0xFFu, s, o);
            if (lane >= o) s += y;
        }
        wsum[lane] = s;
    }
    __syncthreads();
    int woff = (wid == 0) ? 0 : wsum[wid - 1];
    if (i < NN) {
        int excl = d_blkoff[blockIdx.x] + woff + (x - v);
        d_row_ptr[i] = excl;
        d_cursor[i]  = excl;
        d_dinv[i]    = rsqrtf((float)(v + 1));
    }
}

__global__ void fill_csr_kernel(const unsigned* __restrict__ e) {
    int i = blockIdx.x * blockDim.x + threadIdx.x;
    if (i >= EE) return;
    int src, dst;
    if (d_is64) {
        src = (int)e[2 * (size_t)i];
        dst = (int)e[2 * (size_t)(EE + i)];
    } else {
        src = (int)e[i];
        dst = (int)e[EE + i];
    }
    int pos = atomicAdd(&d_cursor[dst], 1);
    d_csr[pos] = src;
}

// ---------------- bf16x3 tensor GEMM: C = dinv[m] * (A @ W) -------------------
#define GBM 128
#define GBN 64
#define GBK 32

__device__ __forceinline__ void mma_bf16(float* d, const unsigned* a, const unsigned* b) {
    asm volatile(
        "mma.sync.aligned.m16n8k16.row.col.f32.bf16.bf16.f32 "
        "{%0,%1,%2,%3}, {%4,%5,%6,%7}, {%8,%9}, {%0,%1,%2,%3};\n"
        : "+f"(d[0]), "+f"(d[1]), "+f"(d[2]), "+f"(d[3])
        : "r"(a[0]), "r"(a[1]), "r"(a[2]), "r"(a[3]),
          "r"(b[0]), "r"(b[1]));
}

// split (a,b) into packed bf16x2 hi word + lo word (a in low half)
__device__ __forceinline__ void split2(float a, float b, unsigned& h, unsigned& l) {
    __nv_bfloat16 ha = __float2bfloat16_rn(a);
    __nv_bfloat16 hb = __float2bfloat16_rn(b);
    __nv_bfloat16 la = __float2bfloat16_rn(a - __bfloat162float(ha));
    __nv_bfloat16 lb = __float2bfloat16_rn(b - __bfloat162float(hb));
    unsigned short sha = *(unsigned short*)&ha, shb = *(unsigned short*)&hb;
    unsigned short sla = *(unsigned short*)&la, slb = *(unsigned short*)&lb;
    h = (unsigned)sha | ((unsigned)shb << 16);
    l = (unsigned)sla | ((unsigned)slb << 16);
}

__device__ __forceinline__ unsigned bpack(const __nv_bfloat16* p0, const __nv_bfloat16* p1) {
    return (unsigned)*(const unsigned short*)p0 |
           ((unsigned)*(const unsigned short*)p1 << 16);
}

__global__ __launch_bounds__(256) void gemm_bf16_kernel(
    const float* __restrict__ Aext, int selA, int selC,
    const float* __restrict__ W, int M, int K, int Nn)
{
    const float* A = Aext ? Aext : bufptr(selA);
    float* C = bufptr(selC);

    // hi/lo planes; strides chosen conflict-free for frag loads
    __shared__ __nv_bfloat16 AsHi[GBM][40], AsLo[GBM][40];
    __shared__ __nv_bfloat16 BsHi[GBK][72], BsLo[GBK][72];

    int tid = threadIdx.x;
    int warp = tid >> 5, lane = tid & 31;
    int g = lane >> 2, tig = lane & 3;
    int warpM = warp >> 1, warpN = warp & 1;    // 4(m) x 2(n) warps, 32x32 each
    int m0 = blockIdx.x * GBM, n0 = blockIdx.y * GBN;

    float acc[2][4][4];
    #pragma unroll
    for (int i = 0; i < 2; i++)
        #pragma unroll
        for (int j = 0; j < 4; j++)
            #pragma unroll
            for (int c = 0; c < 4; c++) acc[i][j][c] = 0.f;

    int ar  = tid >> 3;        // 0..31 row group for A loads
    int ac4 = (tid & 7) * 4;   // k offset 0..28
    int bk  = tid >> 4;        // 0..15 k row for B loads
    int bn4 = (tid & 15) * 4;  // n offset 0..60

    for (int k0 = 0; k0 < K; k0 += GBK) {
        // A tile 128x32: split once into bf16 hi/lo
        #pragma unroll
        for (int rr = 0; rr < 4; rr++) {
            int row = rr * 32 + ar;
            int m = m0 + row;
            float4 v = make_float4(0.f, 0.f, 0.f, 0.f);
            if (m < M) v = *(const float4*)(A + (size_t)m * K + k0 + ac4);
            unsigned h0, l0, h1, l1;
            split2(v.x, v.y, h0, l0);
            split2(v.z, v.w, h1, l1);
            *(uint2*)&AsHi[row][ac4] = make_uint2(h0, h1);
            *(uint2*)&AsLo[row][ac4] = make_uint2(l0, l1);
        }
        // B tile 32x64
        #pragma unroll
        for (int rr = 0; rr < 2; rr++) {
            int kk = rr * 16 + bk;
            float4 v = *(const float4*)(W + (size_t)(k0 + kk) * Nn + n0 + bn4);
            unsigned h0, l0, h1, l1;
            split2(v.x, v.y, h0, l0);
            split2(v.z, v.w, h1, l1);
            *(uint2*)&BsHi[kk][bn4] = make_uint2(h0, h1);
            *(uint2*)&BsLo[kk][bn4] = make_uint2(l0, l1);
        }
        __syncthreads();

        #pragma unroll
        for (int ks = 0; ks < GBK; ks += 16) {
            unsigned aHi[2][4], aLo[2][4];
            #pragma unroll
            for (int ma = 0; ma < 2; ma++) {
                int rb = warpM * 32 + ma * 16;
                aHi[ma][0] = *(const unsigned*)&AsHi[rb + g    ][ks + 2 * tig];
                aHi[ma][1] = *(const unsigned*)&AsHi[rb + g + 8][ks + 2 * tig];
                aHi[ma][2] = *(const unsigned*)&AsHi[rb + g    ][ks + 8 + 2 * tig];
                aHi[ma][3] = *(const unsigned*)&AsHi[rb + g + 8][ks + 8 + 2 * tig];
                aLo[ma][0] = *(const unsigned*)&AsLo[rb + g    ][ks + 2 * tig];
                aLo[ma][1] = *(const unsigned*)&AsLo[rb + g + 8][ks + 2 * tig];
                aLo[ma][2] = *(const unsigned*)&AsLo[rb + g    ][ks + 8 + 2 * tig];
                aLo[ma][3] = *(const unsigned*)&AsLo[rb + g + 8][ks + 8 + 2 * tig];
            }
            unsigned bHi[4][2], bLo[4][2];
            #pragma unroll
            for (int na = 0; na < 4; na++) {
                int nc = warpN * 32 + na * 8 + g;
                bHi[na][0] = bpack(&BsHi[ks + 2 * tig    ][nc], &BsHi[ks + 2 * tig + 1][nc]);
                bHi[na][1] = bpack(&BsHi[ks + 8 + 2 * tig][nc], &BsHi[ks + 9 + 2 * tig][nc]);
                bLo[na][0] = bpack(&BsLo[ks + 2 * tig    ][nc], &BsLo[ks + 2 * tig + 1][nc]);
                bLo[na][1] = bpack(&BsLo[ks + 8 + 2 * tig][nc], &BsLo[ks + 9 + 2 * tig][nc]);
            }
            #pragma unroll
            for (int ma = 0; ma < 2; ma++)
                #pragma unroll
                for (int na = 0; na < 4; na++) {
                    mma_bf16(acc[ma][na], aHi[ma], bHi[na]);
                    mma_bf16(acc[ma][na], aHi[ma], bLo[na]);
                    mma_bf16(acc[ma][na], aLo[ma], bHi[na]);
                }
        }
        __syncthreads();
    }

    #pragma unroll
    for (int ma = 0; ma < 2; ma++) {
        int rb = m0 + warpM * 32 + ma * 16 + g;
        #pragma unroll
        for (int half = 0; half < 2; half++) {
            int row = rb + half * 8;
            if (row < M) {
                float dv = d_dinv[row];
                #pragma unroll
                for (int na = 0; na < 4; na++) {
                    int col = n0 + warpN * 32 + na * 8 + tig * 2;
                    float2 o;
                    o.x = acc[ma][na][half * 2 + 0] * dv;
                    o.y = acc[ma][na][half * 2 + 1] * dv;
                    *(float2*)(C + (size_t)row * Nn + col) = o;
                }
            }
        }
    }
}

// ---------------- threefry (partitionable mode), key(42) ----------------------
#define TF_RND(r) { x0 += x1; x1 = (x1 << r) | (x1 >> (32 - r)); x1 ^= x0; }
__device__ __forceinline__ unsigned threefry_draw(unsigned t) {
    unsigned x0 = 0u, x1 = t;
    const unsigned ks1 = 42u, ks2 = 42u ^ 0x1BD11BDAu;
    x1 += ks1;
    TF_RND(13) TF_RND(15) TF_RND(26) TF_RND(6)   x0 += ks1; x1 += ks2 + 1u;
    TF_RND(17) TF_RND(29) TF_RND(16) TF_RND(24)  x0 += ks2; x1 += 0u  + 2u;
    TF_RND(13) TF_RND(15) TF_RND(26) TF_RND(6)   x0 += 0u;  x1 += ks1 + 3u;
    TF_RND(17) TF_RND(29) TF_RND(16) TF_RND(24)  x0 += ks1; x1 += ks2 + 4u;
    TF_RND(13) TF_RND(15) TF_RND(26) TF_RND(6)   x0 += ks2; x1 += 0u  + 5u;
    return x0 ^ x1;
}

// ---------------- CSR aggregation + bias + leaky_relu (+ fused dropout) ------
// blockDim = 128; TPN = F/4 threads per node; G = 128/TPN nodes per block
__global__ void aggregate_kernel(int selIn, int selOut,
                                 const float* __restrict__ bias,
                                 int F, int drop)
{
    const float4* h4 = (const float4*)bufptr(selIn);
    float4* out4 = (float4*)bufptr(selOut);
    int TPN = F >> 2;
    int sub = threadIdx.x / TPN;
    int f4  = threadIdx.x - sub * TPN;
    int G   = blockDim.x / TPN;
    int node = blockIdx.x * G + sub;
    if (node >= NN) return;

    int p0 = d_row_ptr[node], p1 = d_row_ptr[node + 1];
    float4 acc = h4[(size_t)node * TPN + f4];   // self-loop (pre-scaled by dinv)
    int j = p0;
    for (; j + 3 < p1; j += 4) {
        int s0 = d_csr[j], s1 = d_csr[j + 1], s2 = d_csr[j + 2], s3 = d_csr[j + 3];
        float4 v0 = h4[(size_t)s0 * TPN + f4];
        float4 v1 = h4[(size_t)s1 * TPN + f4];
        float4 v2 = h4[(size_t)s2 * TPN + f4];
        float4 v3 = h4[(size_t)s3 * TPN + f4];
        acc.x += v0.x + v1.x + v2.x + v3.x;
        acc.y += v0.y + v1.y + v2.y + v3.y;
        acc.z += v0.z + v1.z + v2.z + v3.z;
        acc.w += v0.w + v1.w + v2.w + v3.w;
    }
    for (; j < p1; j++) {
        int s = d_csr[j];
        float4 v = h4[(size_t)s * TPN + f4];
        acc.x += v.x; acc.y += v.y; acc.z += v.z; acc.w += v.w;
    }
    float dv = d_dinv[node];
    float4 bb = ((const float4*)bias)[f4];
    float4 v;
    v.x = dv * acc.x + bb.x;  v.y = dv * acc.y + bb.y;
    v.z = dv * acc.z + bb.z;  v.w = dv * acc.w + bb.w;
    v.x = (v.x >= 0.f) ? v.x : 0.01f * v.x;
    v.y = (v.y >= 0.f) ? v.y : 0.01f * v.y;
    v.z = (v.z >= 0.f) ? v.z : 0.01f * v.z;
    v.w = (v.w >= 0.f) ? v.w : 0.01f * v.w;
    if (drop) {   // only for F=64 layer: t = node*64 + f
        unsigned t0 = (unsigned)node * 64u + (unsigned)f4 * 4u;
        v.x = (threefry_draw(t0 + 0u) >> 31) ? 0.f : v.x * 2.f;
        v.y = (threefry_draw(t0 + 1u) >> 31) ? 0.f : v.y * 2.f;
        v.z = (threefry_draw(t0 + 2u) >> 31) ? 0.f : v.z * 2.f;
        v.w = (threefry_draw(t0 + 3u) >> 31) ? 0.f : v.w * 2.f;
    }
    out4[(size_t)node * TPN + f4] = v;
}

// ---------------- final tiny GEMM: out[M,10] = h[M,64] @ W5[64,10] + b5 -------
__global__ __launch_bounds__(256) void final_gemm_kernel(
    int sel, const float* __restrict__ W, const float* __restrict__ b,
    float* __restrict__ out, int M)
{
    const float* h = bufptr(sel);
    __shared__ float Xs[64 * 68];      // stride 68 -> conflict-free dot loads
    __shared__ float Ws[64 * 10];
    __shared__ float bs[10];
    int t = threadIdx.x;
    int m0 = blockIdx.x * 64;

    for (int idx = t; idx < 640; idx += 256) Ws[idx] = W[idx];
    if (t < 10) bs[t] = b[t];
    for (int idx = t; idx < 64 * 16; idx += 256) {
        int row = idx >> 4, c4 = idx & 15;
        int m = m0 + row;
        float4 v = make_float4(0.f, 0.f, 0.f, 0.f);
        if (m < M) v = ((const float4*)h)[(size_t)m * 16 + c4];
        *(float4*)&Xs[row * 68 + c4 * 4] = v;
    }
    __syncthreads();

    for (int o = t; o < 640; o += 256) {
        int row = o / 10, col = o % 10;
        int m = m0 + row;
        if (m < M) {
            float s = bs[col];
            #pragma unroll 8
            for (int k = 0; k < 64; k++)
                s += Xs[row * 68 + k] * Ws[k * 10 + col];
            out[(size_t)m * 10 + col] = s;
        }
    }
}

// ---------------- launch ----------------
extern "C" void kernel_launch(void* const* d_in, const int* in_sizes, int n_in,
                              void* d_out, int out_size)
{
    const float*    x     = (const float*)d_in[0];
    const unsigned* edges = (const unsigned*)d_in[1];
    const float* W1 = (const float*)d_in[2];  const float* b1 = (const float*)d_in[3];
    const float* W2 = (const float*)d_in[4];  const float* b2 = (const float*)d_in[5];
    const float* W3 = (const float*)d_in[6];  const float* b3 = (const float*)d_in[7];
    const float* W4 = (const float*)d_in[8];  const float* b4 = (const float*)d_in[9];
    const float* W5 = (const float*)d_in[10]; const float* b5 = (const float*)d_in[11];

    const int M = NN;
    const int gm = (M + GBM - 1) / GBM;   // 391
    const int gfin = (M + 63) / 64;       // 782

    detect_kernel<<<1, 32>>>(edges);
    zero_deg_kernel<<<(NN + 255) / 256, 256>>>();
    count_deg_kernel<<<(EE + 255) / 256, 256>>>(edges);
    deg_blocksum_kernel<<<NBLK, SCAN_B>>>();
    scan_blocks_kernel<<<1, 256>>>();
    scatter_scan_kernel<<<NBLK, SCAN_B>>>();
    fill_csr_kernel<<<(EE + 255) / 256, 256>>>(edges);

    // layer 1: X(ext,256) -> A ; agg -> B   (F=256, 2 nodes/block)
    gemm_bf16_kernel<<<dim3(gm, 4), 256>>>(x, 0, 0, W1, M, 256, 256);
    aggregate_kernel<<<(NN + 1) / 2, 128>>>(0, 1, b1, 256, 0);
    // layer 2
    gemm_bf16_kernel<<<dim3(gm, 4), 256>>>(nullptr, 1, 0, W2, M, 256, 256);
    aggregate_kernel<<<(NN + 1) / 2, 128>>>(0, 1, b2, 256, 0);
    // layer 3: 256 -> 128  (F=128, 4 nodes/block)
    gemm_bf16_kernel<<<dim3(gm, 2), 256>>>(nullptr, 1, 0, W3, M, 256, 128);
    aggregate_kernel<<<(NN + 3) / 4, 128>>>(0, 1, b3, 128, 0);
    // layer 4: 128 -> 64   (F=64, 8 nodes/block) + fused dropout
    gemm_bf16_kernel<<<dim3(gm, 1), 256>>>(nullptr, 1, 0, W4, M, 128, 64);
    aggregate_kernel<<<(NN + 7) / 8, 128>>>(0, 1, b4, 64, 1);
    // final: B @ W5 + b5 -> d_out
    final_gemm_kernel<<<gfin, 256>>>(1, W5, b5, (float*)d_out, M);
}